// round 5
// baseline (speedup 1.0000x reference)
#include <cuda_runtime.h>
#include <cuda_bf16.h>

// B=16, NX=2048, HD=64 -> H=32, T=8192. No softmax.
#define HD      64
#define T_CTX   8192
#define H_HEADS 32
#define B_SZ    16
#define NBH     (B_SZ * H_HEADS)      // 512
#define SPLITS  2
#define NTHR    128                   // 4 warps
#define NWARP   (NTHR / 32)
#define T_SPLIT (T_CTX / SPLITS)      // 4096
#define T_WARP  (T_SPLIT / NWARP)     // 1024
#define TILE    128                   // t's per warp-iteration
#define NTILE   (T_WARP / TILE)       // 8

// ---- phase A: w[t0 + 4*lane + i] = sum_d q[d] * K[d, t0+4*lane+i] ----
__device__ __forceinline__ float4 phaseA(const float* __restrict__ Kb,
                                         const float* __restrict__ sq,
                                         int t0, int lane)
{
    float4 wv = make_float4(0.f, 0.f, 0.f, 0.f);
    const float4* kp = (const float4*)(Kb + t0) + lane;
    #pragma unroll
    for (int d = 0; d < HD; d++) {
        float4 kk = __ldcs(kp + (size_t)d * (T_CTX / 4));
        float qd = sq[d];
        wv.x = fmaf(qd, kk.x, wv.x);
        wv.y = fmaf(qd, kk.y, wv.y);
        wv.z = fmaf(qd, kk.z, wv.z);
        wv.w = fmaf(qd, kk.w, wv.w);
    }
    return wv;
}

__global__ void zero_out_kernel(float* __restrict__ out)
{
    out[blockIdx.x * 256 + threadIdx.x] = 0.f;
}

__global__ __launch_bounds__(NTHR, 8)
void attn_main_kernel(const float* __restrict__ q,
                      const float* __restrict__ k,
                      const float* __restrict__ v,
                      const float* __restrict__ pk,   // [B,H,HD,T]  (t contiguous)
                      const float* __restrict__ pv,   // [B,H,T,HD]  (d contiguous)
                      float* __restrict__ out)        // zero-initialized
{
    __shared__ float sq[HD];
    __shared__ float sw[2][NWARP][TILE];      // double-buffered per-warp w
    __shared__ float sred[2 * NWARP][HD];
    __shared__ float s_wcur;

    const int tid  = threadIdx.x;
    const int lane = tid & 31;
    const int wid  = tid >> 5;
    const int par  = lane >> 4;               // row parity within step
    const int dx   = lane & 15;               // d-quad index
    const int bh   = blockIdx.x >> 1;
    const int half = blockIdx.x & 1;

    const float* Kb = pk + (size_t)bh * HD * T_CTX;
    const float* Vb = pv + (size_t)bh * T_CTX * HD;

    if (tid < HD) sq[tid] = q[(size_t)bh * HD + tid];

    // current-token weight (only half-0 block needs it); warp 1 computes it
    if (half == 0 && wid == 1) {
        size_t base = (size_t)bh * HD;
        float p = q[base + lane] * k[base + lane]
                + q[base + lane + 32] * k[base + lane + 32];
        #pragma unroll
        for (int off = 16; off > 0; off >>= 1)
            p += __shfl_down_sync(0xffffffffu, p, off);
        if (lane == 0) s_wcur = p;
    }
    __syncthreads();

    const int tbase = half * T_SPLIT + wid * T_WARP;
    float4 acc = make_float4(0.f, 0.f, 0.f, 0.f);  // lane: d = 4*dx.., rows parity par

    // prologue: w for tile 0 into buffer 0
    {
        float4 w0 = phaseA(Kb, sq, tbase, lane);
        *(float4*)(&sw[0][wid][lane * 4]) = w0;
    }
    __syncwarp();

    int buf = 0;
    #pragma unroll 1
    for (int tile = 0; tile < NTILE; tile++) {
        const int t0 = tbase + tile * TILE;

        // pipeline: compute w(tile+1) while B consumes w(tile)
        float4 wn;
        if (tile + 1 < NTILE)
            wn = phaseA(Kb, sq, t0 + TILE, lane);

        // phase B: rows r = 2*jj + par; lane loads float4 of V at d=4*dx.
        const float4* vp = (const float4*)(Vb + (size_t)t0 * HD) + dx;
        const float* wrow = &sw[buf][wid][par];
        #pragma unroll 8
        for (int jj = 0; jj < TILE / 2; jj++) {
            float  wt = wrow[2 * jj];
            float4 vv = __ldcs(vp + (2 * jj + par) * (HD / 4));
            acc.x = fmaf(wt, vv.x, acc.x);
            acc.y = fmaf(wt, vv.y, acc.y);
            acc.z = fmaf(wt, vv.z, acc.z);
            acc.w = fmaf(wt, vv.w, acc.w);
        }

        if (tile + 1 < NTILE) {
            *(float4*)(&sw[buf ^ 1][wid][lane * 4]) = wn;
        }
        __syncwarp();
        buf ^= 1;
    }

    // reduction: 8 partials (4 warps x 2 parities) per d, then one atomic add.
    *(float4*)(&sred[wid * 2 + par][dx * 4]) = acc;
    __syncthreads();
    if (tid < HD) {
        float s = 0.f;
        #pragma unroll
        for (int w = 0; w < 2 * NWARP; w++) s += sred[w][tid];
        size_t o = (size_t)bh * HD + tid;
        if (half == 0) s = fmaf(s_wcur, v[o], s);
        atomicAdd(&out[o], s);   // exactly 2 commutative adds per cell -> deterministic
    }
}

extern "C" void kernel_launch(void* const* d_in, const int* in_sizes, int n_in,
                              void* d_out, int out_size) {
    const float* q  = (const float*)d_in[0];
    const float* k  = (const float*)d_in[1];
    const float* v  = (const float*)d_in[2];
    const float* pk = (const float*)d_in[3];
    const float* pv = (const float*)d_in[4];
    float* out = (float*)d_out;

    zero_out_kernel<<<NBH * HD / 256, 256>>>(out);
    attn_main_kernel<<<NBH * SPLITS, NTHR>>>(q, k, v, pk, pv, out);
}

// round 6
// speedup vs baseline: 1.0189x; 1.0189x over previous
#include <cuda_runtime.h>
#include <cuda_bf16.h>

// B=16, NX=2048, HD=64 -> H=32, T=8192. No softmax.
#define HD      64
#define T_CTX   8192
#define H_HEADS 32
#define B_SZ    16
#define NBH     (B_SZ * H_HEADS)      // 512
#define SPLITS  2
#define NTHR    128                   // 4 warps
#define NWARP   (NTHR / 32)
#define T_SPLIT (T_CTX / SPLITS)      // 4096
#define T_WARP  (T_SPLIT / NWARP)     // 1024
#define TILE    128                   // t's per warp-iteration
#define NTILE   (T_WARP / TILE)       // 8

// ---- phase A: w[t0 + 4*lane + i] = sum_d q[d] * K[d, t0+4*lane+i] ----
__device__ __forceinline__ float4 phaseA(const float* __restrict__ Kb,
                                         const float* __restrict__ sq,
                                         int t0, int lane)
{
    float4 wv = make_float4(0.f, 0.f, 0.f, 0.f);
    const float4* kp = (const float4*)(Kb + t0) + lane;
    #pragma unroll
    for (int d = 0; d < HD; d++) {
        float4 kk = kp[(size_t)d * (T_CTX / 4)];
        float qd = sq[d];
        wv.x = fmaf(qd, kk.x, wv.x);
        wv.y = fmaf(qd, kk.y, wv.y);
        wv.z = fmaf(qd, kk.z, wv.z);
        wv.w = fmaf(qd, kk.w, wv.w);
    }
    return wv;
}

__global__ __launch_bounds__(NTHR, 8)
void attn_main_kernel(const float* __restrict__ q,
                      const float* __restrict__ k,
                      const float* __restrict__ v,
                      const float* __restrict__ pk,   // [B,H,HD,T]  (t contiguous)
                      const float* __restrict__ pv,   // [B,H,T,HD]  (d contiguous)
                      float* __restrict__ out)        // zero-initialized (memset node)
{
    __shared__ float sq[HD];
    __shared__ float sw[2][NWARP][TILE];      // double-buffered per-warp w
    __shared__ float sred[2 * NWARP][HD];
    __shared__ float s_wcur;

    const int tid  = threadIdx.x;
    const int lane = tid & 31;
    const int wid  = tid >> 5;
    const int par  = lane >> 4;               // row parity within step
    const int dx   = lane & 15;               // d-quad index
    const int bh   = blockIdx.x >> 1;
    const int half = blockIdx.x & 1;

    const float* Kb = pk + (size_t)bh * HD * T_CTX;
    const float* Vb = pv + (size_t)bh * T_CTX * HD;

    if (tid < HD) sq[tid] = q[(size_t)bh * HD + tid];

    // current-token weight (only half-0 block applies it); warp 1 computes it
    if (half == 0 && wid == 1) {
        size_t base = (size_t)bh * HD;
        float p = q[base + lane] * k[base + lane]
                + q[base + lane + 32] * k[base + lane + 32];
        #pragma unroll
        for (int off = 16; off > 0; off >>= 1)
            p += __shfl_down_sync(0xffffffffu, p, off);
        if (lane == 0) s_wcur = p;
    }
    __syncthreads();

    const int tbase = half * T_SPLIT + wid * T_WARP;
    float4 acc = make_float4(0.f, 0.f, 0.f, 0.f);  // lane: d = 4*dx.., rows parity par

    // prologue: w for tile 0 into buffer 0
    {
        float4 w0 = phaseA(Kb, sq, tbase, lane);
        *(float4*)(&sw[0][wid][lane * 4]) = w0;
    }
    __syncwarp();

    int buf = 0;
    #pragma unroll 1
    for (int tile = 0; tile < NTILE; tile++) {
        const int t0 = tbase + tile * TILE;

        // pipeline: compute w(tile+1) while B consumes w(tile)
        float4 wn;
        if (tile + 1 < NTILE)
            wn = phaseA(Kb, sq, t0 + TILE, lane);

        // phase B: rows r = 2*jj + par; lane loads float4 of V at d=4*dx.
        const float4* vp = (const float4*)(Vb + (size_t)t0 * HD) + dx;
        const float* wrow = &sw[buf][wid][par];
        #pragma unroll 8
        for (int jj = 0; jj < TILE / 2; jj++) {
            float  wt = wrow[2 * jj];
            float4 vv = vp[(2 * jj + par) * (HD / 4)];
            acc.x = fmaf(wt, vv.x, acc.x);
            acc.y = fmaf(wt, vv.y, acc.y);
            acc.z = fmaf(wt, vv.z, acc.z);
            acc.w = fmaf(wt, vv.w, acc.w);
        }

        if (tile + 1 < NTILE) {
            *(float4*)(&sw[buf ^ 1][wid][lane * 4]) = wn;
        }
        __syncwarp();
        buf ^= 1;
    }

    // reduction: 8 partials (4 warps x 2 parities) per d, then one atomic add.
    *(float4*)(&sred[wid * 2 + par][dx * 4]) = acc;
    __syncthreads();
    if (tid < HD) {
        float s = 0.f;
        #pragma unroll
        for (int w = 0; w < 2 * NWARP; w++) s += sred[w][tid];
        size_t o = (size_t)bh * HD + tid;
        if (half == 0) s = fmaf(s_wcur, v[o], s);
        atomicAdd(&out[o], s);   // exactly 2 commutative adds per cell -> deterministic
    }
}

extern "C" void kernel_launch(void* const* d_in, const int* in_sizes, int n_in,
                              void* d_out, int out_size) {
    const float* q  = (const float*)d_in[0];
    const float* k  = (const float*)d_in[1];
    const float* v  = (const float*)d_in[2];
    const float* pk = (const float*)d_in[3];
    const float* pv = (const float*)d_in[4];
    float* out = (float*)d_out;

    cudaMemsetAsync(out, 0, (size_t)NBH * HD * sizeof(float));
    attn_main_kernel<<<NBH * SPLITS, NTHR>>>(q, k, v, pk, pv, out);
}

// round 7
// speedup vs baseline: 1.0488x; 1.0293x over previous
#include <cuda_runtime.h>
#include <cuda_bf16.h>

// B=16, NX=2048, HD=64 -> H=32, T=8192. No softmax.
#define HD      64
#define T_CTX   8192
#define H_HEADS 32
#define B_SZ    16
#define NBH     (B_SZ * H_HEADS)      // 512
#define SPLITS  2
#define NTHR    128                   // 4 warps
#define NWARP   (NTHR / 32)
#define T_SPLIT (T_CTX / SPLITS)      // 4096
#define TILE    128                   // t's per warp-tile
#define NTILE   (T_SPLIT / (TILE * NWARP))  // 8 tiles per warp, warp-interleaved

// ---- phase A: w[t0 + 4*lane + i] = sum_d q[d] * K[d, t0+4*lane+i] ----
__device__ __forceinline__ float4 phaseA(const float* __restrict__ Kb,
                                         const float* __restrict__ sq,
                                         int t0, int lane)
{
    float4 wv = make_float4(0.f, 0.f, 0.f, 0.f);
    const float4* kp = (const float4*)(Kb + t0) + lane;
    #pragma unroll
    for (int d = 0; d < HD; d++) {
        float4 kk = kp[(size_t)d * (T_CTX / 4)];
        float qd = sq[d];
        wv.x = fmaf(qd, kk.x, wv.x);
        wv.y = fmaf(qd, kk.y, wv.y);
        wv.z = fmaf(qd, kk.z, wv.z);
        wv.w = fmaf(qd, kk.w, wv.w);
    }
    return wv;
}

__global__ __launch_bounds__(NTHR, 8)
void attn_main_kernel(const float* __restrict__ q,
                      const float* __restrict__ k,
                      const float* __restrict__ v,
                      const float* __restrict__ pk,   // [B,H,HD,T]  (t contiguous)
                      const float* __restrict__ pv,   // [B,H,T,HD]  (d contiguous)
                      float* __restrict__ out)        // zero-initialized (memset node)
{
    __shared__ float sq[HD];
    __shared__ float sw[2][NWARP][TILE];      // double-buffered per-warp w
    __shared__ float sred[2 * NWARP][HD];
    __shared__ float s_wcur;

    const int tid  = threadIdx.x;
    const int lane = tid & 31;
    const int wid  = tid >> 5;
    const int par  = lane >> 4;               // row parity within step
    const int dx   = lane & 15;               // d-quad index
    const int bh   = blockIdx.x >> 1;
    const int half = blockIdx.x & 1;

    const float* Kb = pk + (size_t)bh * HD * T_CTX;
    const float* Vb = pv + (size_t)bh * T_CTX * HD;

    if (tid < HD) sq[tid] = q[(size_t)bh * HD + tid];

    // current-token weight (only half-0 block applies it); warp 1 computes it
    if (half == 0 && wid == 1) {
        size_t base = (size_t)bh * HD;
        float p = q[base + lane] * k[base + lane]
                + q[base + lane + 32] * k[base + lane + 32];
        #pragma unroll
        for (int off = 16; off > 0; off >>= 1)
            p += __shfl_down_sync(0xffffffffu, p, off);
        if (lane == 0) s_wcur = p;
    }
    __syncthreads();

    // Warp-interleaved tiles: warp w owns t = tbase + (i*NWARP + w)*TILE.
    // All 4 warps read adjacent 512B chunks per d-step -> 2KB contiguous bursts.
    const int tbase = half * T_SPLIT;
    float4 acc = make_float4(0.f, 0.f, 0.f, 0.f);  // lane: d = 4*dx.., rows parity par

    // prologue: w for tile 0 into buffer 0
    {
        float4 w0 = phaseA(Kb, sq, tbase + wid * TILE, lane);
        *(float4*)(&sw[0][wid][lane * 4]) = w0;
    }
    __syncwarp();

    int buf = 0;
    #pragma unroll 1
    for (int tile = 0; tile < NTILE; tile++) {
        const int t0 = tbase + (tile * NWARP + wid) * TILE;

        // pipeline: compute w(tile+1) while B consumes w(tile)
        float4 wn;
        if (tile + 1 < NTILE)
            wn = phaseA(Kb, sq, t0 + NWARP * TILE, lane);

        // phase B: rows r = 2*jj + par; lane loads float4 of V at d=4*dx.
        const float4* vp = (const float4*)(Vb + (size_t)t0 * HD) + dx;
        const float* wrow = &sw[buf][wid][par];
        #pragma unroll 8
        for (int jj = 0; jj < TILE / 2; jj++) {
            float  wt = wrow[2 * jj];
            float4 vv = vp[(2 * jj + par) * (HD / 4)];
            acc.x = fmaf(wt, vv.x, acc.x);
            acc.y = fmaf(wt, vv.y, acc.y);
            acc.z = fmaf(wt, vv.z, acc.z);
            acc.w = fmaf(wt, vv.w, acc.w);
        }

        if (tile + 1 < NTILE) {
            *(float4*)(&sw[buf ^ 1][wid][lane * 4]) = wn;
        }
        __syncwarp();
        buf ^= 1;
    }

    // reduction: 8 partials (4 warps x 2 parities) per d, then one atomic add.
    *(float4*)(&sred[wid * 2 + par][dx * 4]) = acc;
    __syncthreads();
    if (tid < HD) {
        float s = 0.f;
        #pragma unroll
        for (int w = 0; w < 2 * NWARP; w++) s += sred[w][tid];
        size_t o = (size_t)bh * HD + tid;
        if (half == 0) s = fmaf(s_wcur, v[o], s);
        atomicAdd(&out[o], s);   // exactly 2 commutative adds per cell -> deterministic
    }
}

extern "C" void kernel_launch(void* const* d_in, const int* in_sizes, int n_in,
                              void* d_out, int out_size) {
    const float* q  = (const float*)d_in[0];
    const float* k  = (const float*)d_in[1];
    const float* v  = (const float*)d_in[2];
    const float* pk = (const float*)d_in[3];
    const float* pv = (const float*)d_in[4];
    float* out = (float*)d_out;

    cudaMemsetAsync(out, 0, (size_t)NBH * HD * sizeof(float));
    attn_main_kernel<<<NBH * SPLITS, NTHR>>>(q, k, v, pk, pv, out);
}

// round 8
// speedup vs baseline: 1.0630x; 1.0136x over previous
#include <cuda_runtime.h>
#include <cuda_bf16.h>

// B=16, NX=2048, HD=64 -> H=32, T=8192. No softmax.
#define HD      64
#define T_CTX   8192
#define H_HEADS 32
#define B_SZ    16
#define NBH     (B_SZ * H_HEADS)      // 512
#define SPLITS  2
#define NTHR    128                   // 4 warps
#define NWARP   (NTHR / 32)
#define T_SPLIT (T_CTX / SPLITS)      // 4096
#define TILE    256                   // t's per warp-tile (1KB/warp per d-step)
#define NTILE   (T_SPLIT / (TILE * NWARP))  // 4 tiles per warp, warp-interleaved

// ---- phase A: w[t0 .. t0+255] = sum_d q[d] * K[d, .]  (2 float4 per lane) ----
__device__ __forceinline__ void phaseA(const float* __restrict__ Kb,
                                       const float* __restrict__ sq,
                                       int t0, int lane,
                                       float4& w0, float4& w1)
{
    float4 a = make_float4(0.f, 0.f, 0.f, 0.f);
    float4 b = make_float4(0.f, 0.f, 0.f, 0.f);
    const float4* kp = (const float4*)(Kb + t0) + lane;
    #pragma unroll
    for (int d = 0; d < HD; d++) {
        float4 k0 = kp[(size_t)d * (T_CTX / 4)];
        float4 k1 = kp[(size_t)d * (T_CTX / 4) + 32];
        float qd = sq[d];
        a.x = fmaf(qd, k0.x, a.x);  a.y = fmaf(qd, k0.y, a.y);
        a.z = fmaf(qd, k0.z, a.z);  a.w = fmaf(qd, k0.w, a.w);
        b.x = fmaf(qd, k1.x, b.x);  b.y = fmaf(qd, k1.y, b.y);
        b.z = fmaf(qd, k1.z, b.z);  b.w = fmaf(qd, k1.w, b.w);
    }
    w0 = a; w1 = b;
}

__global__ __launch_bounds__(NTHR, 8)
void attn_main_kernel(const float* __restrict__ q,
                      const float* __restrict__ k,
                      const float* __restrict__ v,
                      const float* __restrict__ pk,   // [B,H,HD,T]  (t contiguous)
                      const float* __restrict__ pv,   // [B,H,T,HD]  (d contiguous)
                      float* __restrict__ out)        // zero-initialized (memset node)
{
    __shared__ float sq[HD];
    __shared__ float sw[2][NWARP][TILE];      // double-buffered per-warp w (8KB)
    __shared__ float sred[2 * NWARP][HD];
    __shared__ float s_wcur;

    const int tid  = threadIdx.x;
    const int lane = tid & 31;
    const int wid  = tid >> 5;
    const int par  = lane >> 4;               // row parity within step
    const int dx   = lane & 15;               // d-quad index
    const int bh   = blockIdx.x >> 1;
    const int half = blockIdx.x & 1;

    const float* Kb = pk + (size_t)bh * HD * T_CTX;
    const float* Vb = pv + (size_t)bh * T_CTX * HD;

    if (tid < HD) sq[tid] = q[(size_t)bh * HD + tid];

    // current-token weight (only half-0 block applies it); warp 1 computes it
    if (half == 0 && wid == 1) {
        size_t base = (size_t)bh * HD;
        float p = q[base + lane] * k[base + lane]
                + q[base + lane + 32] * k[base + lane + 32];
        #pragma unroll
        for (int off = 16; off > 0; off >>= 1)
            p += __shfl_down_sync(0xffffffffu, p, off);
        if (lane == 0) s_wcur = p;
    }
    __syncthreads();

    // Warp-interleaved tiles: warp w owns t = tbase + (i*NWARP + w)*TILE.
    // 4 warps x 1KB adjacent per d-step -> 4KB contiguous CTA bursts.
    const int tbase = half * T_SPLIT;
    float4 acc = make_float4(0.f, 0.f, 0.f, 0.f);  // lane: d = 4*dx.., rows parity par

    // prologue: w for tile 0 into buffer 0
    {
        float4 w0, w1;
        phaseA(Kb, sq, tbase + wid * TILE, lane, w0, w1);
        *(float4*)(&sw[0][wid][lane * 4])       = w0;
        *(float4*)(&sw[0][wid][128 + lane * 4]) = w1;
    }
    __syncwarp();

    int buf = 0;
    #pragma unroll 1
    for (int tile = 0; tile < NTILE; tile++) {
        const int t0 = tbase + (tile * NWARP + wid) * TILE;

        // pipeline: compute w(tile+1) while B consumes w(tile)
        float4 wn0, wn1;
        if (tile + 1 < NTILE)
            phaseA(Kb, sq, t0 + NWARP * TILE, lane, wn0, wn1);

        // phase B: rows r = 2*jj + par; lane loads float4 of V at d=4*dx.
        const float4* vp = (const float4*)(Vb + (size_t)t0 * HD) + dx;
        const float* wrow = &sw[buf][wid][par];
        #pragma unroll 8
        for (int jj = 0; jj < TILE / 2; jj++) {
            float  wt = wrow[2 * jj];
            float4 vv = vp[(2 * jj + par) * (HD / 4)];
            acc.x = fmaf(wt, vv.x, acc.x);
            acc.y = fmaf(wt, vv.y, acc.y);
            acc.z = fmaf(wt, vv.z, acc.z);
            acc.w = fmaf(wt, vv.w, acc.w);
        }

        if (tile + 1 < NTILE) {
            *(float4*)(&sw[buf ^ 1][wid][lane * 4])       = wn0;
            *(float4*)(&sw[buf ^ 1][wid][128 + lane * 4]) = wn1;
        }
        __syncwarp();
        buf ^= 1;
    }

    // reduction: 8 partials (4 warps x 2 parities) per d, then one atomic add.
    *(float4*)(&sred[wid * 2 + par][dx * 4]) = acc;
    __syncthreads();
    if (tid < HD) {
        float s = 0.f;
        #pragma unroll
        for (int w = 0; w < 2 * NWARP; w++) s += sred[w][tid];
        size_t o = (size_t)bh * HD + tid;
        if (half == 0) s = fmaf(s_wcur, v[o], s);
        atomicAdd(&out[o], s);   // exactly 2 commutative adds per cell -> deterministic
    }
}

extern "C" void kernel_launch(void* const* d_in, const int* in_sizes, int n_in,
                              void* d_out, int out_size) {
    const float* q  = (const float*)d_in[0];
    const float* k  = (const float*)d_in[1];
    const float* v  = (const float*)d_in[2];
    const float* pk = (const float*)d_in[3];
    const float* pv = (const float*)d_in[4];
    float* out = (float*)d_out;

    cudaMemsetAsync(out, 0, (size_t)NBH * HD * sizeof(float));
    attn_main_kernel<<<NBH * SPLITS, NTHR>>>(q, k, v, pk, pv, out);
}